// round 1
// baseline (speedup 1.0000x reference)
#include <cuda_runtime.h>
#include <cuda_bf16.h>

#define N_NODES 50000
#define N_EDGES 800000
#define E_TOT   850000    // edges + self loops
#define N_GRAPHS 256
#define NEG_SLOPE 0.2f

// ---------------- scratch (device globals; no allocation allowed) ----------------
__device__ float4 g_h1  [N_NODES * 32];   // [N,128] layer-1 features
__device__ float4 g_out1[N_NODES * 32];   // [N,128] layer-1 aggregated
__device__ float4 g_as1 [N_NODES];        // [N,4] alpha_src heads
__device__ float4 g_ad1 [N_NODES];        // [N,4] alpha_dst heads
__device__ float4 g_den1[N_NODES];        // [N,4] softmax denoms
__device__ float4 g_ew1 [E_TOT];          // [E,4] exp(leaky(e)) per head
__device__ float4 g_h2  [N_NODES * 8];    // [N,32] layer-2 features
__device__ float4 g_out2[N_NODES * 8];    // [N,32] layer-2 aggregated
__device__ float  g_as2 [N_NODES];
__device__ float  g_ad2 [N_NODES];
__device__ float  g_den2[N_NODES];
__device__ float  g_ew2 [E_TOT];

__device__ __forceinline__ float lrelu(float t) {
    return t > 0.f ? t : NEG_SLOPE * t;
}

// ---------------- kernel 1: h1 = x@W1, alphas, zero accumulators ----------------
// one block (128 threads) per node; warp w handles head w
__global__ void k_node1(const float* __restrict__ x, const float* __restrict__ W1,
                        const float* __restrict__ as1, const float* __restrict__ ad1)
{
    int node = blockIdx.x;
    int f = threadIdx.x;               // 0..127
    float x0 = x[node * 2], x1 = x[node * 2 + 1];
    float h = x0 * W1[f] + x1 * W1[128 + f];
    ((float*)g_h1)[node * 128 + f] = h;
    ((float*)g_out1)[node * 128 + f] = 0.f;

    int head = f >> 5, lane = f & 31;
    float vs = h * as1[f];             // a_src1 is [4,32] row-major => index f
    float vd = h * ad1[f];
#pragma unroll
    for (int o = 16; o > 0; o >>= 1) {
        vs += __shfl_down_sync(0xffffffffu, vs, o);
        vd += __shfl_down_sync(0xffffffffu, vd, o);
    }
    if (lane == 0) {
        ((float*)g_as1)[node * 4 + head] = vs;
        ((float*)g_ad1)[node * 4 + head] = vd;
        ((float*)g_den1)[node * 4 + head] = 0.f;
    }
}

// ---------------- kernel 2: layer-1 edge exp + denom (all 4 heads per thread) ---
__global__ void k_edge1a(const int* __restrict__ ei)
{
    int e = blockIdx.x * blockDim.x + threadIdx.x;
    if (e >= E_TOT) return;
    int s, d;
    if (e < N_EDGES) { s = ei[e]; d = ei[N_EDGES + e]; }
    else             { s = e - N_EDGES; d = s; }

    float4 a = g_as1[s];
    float4 b = g_ad1[d];
    float4 w;
    w.x = __expf(lrelu(a.x + b.x));
    w.y = __expf(lrelu(a.y + b.y));
    w.z = __expf(lrelu(a.z + b.z));
    w.w = __expf(lrelu(a.w + b.w));
    g_ew1[e] = w;
    atomicAdd(&g_den1[d], w);          // vector fp32x4 RED (sm_90+)
}

// ---------------- kernel 3: layer-1 aggregation (warp per edge, float4 atomics) -
__global__ void k_edge1b(const int* __restrict__ ei)
{
    int w = (blockIdx.x * blockDim.x + threadIdx.x) >> 5;
    if (w >= E_TOT) return;
    int lane = threadIdx.x & 31;
    int s, d;
    if (w < N_EDGES) { s = ei[w]; d = ei[N_EDGES + w]; }
    else             { s = w - N_EDGES; d = s; }

    int head = lane >> 3;              // lane covers features [lane*4 .. lane*4+3]
    float att = ((const float*)g_ew1)[w * 4 + head] /
                (((const float*)g_den1)[d * 4 + head] + 1e-16f);
    float4 hv = g_h1[s * 32 + lane];
    float4 v = make_float4(att * hv.x, att * hv.y, att * hv.z, att * hv.w);
    atomicAdd(&g_out1[d * 32 + lane], v);
}

// ---------------- kernel 4: elu(out1+b1), h2 = act@W2, alpha2, zero layer-2 -----
__global__ void k_node2(const float* __restrict__ b1, const float* __restrict__ W2,
                        const float* __restrict__ as2, const float* __restrict__ ad2)
{
    __shared__ float act[128];
    int node = blockIdx.x;
    int f = threadIdx.x;
    float v = ((const float*)g_out1)[node * 128 + f] + b1[f];
    v = v > 0.f ? v : (__expf(v) - 1.f);
    act[f] = v;
    __syncthreads();
    if (f < 32) {
        float acc = 0.f;
#pragma unroll 8
        for (int k = 0; k < 128; k++)
            acc += act[k] * W2[k * 32 + f];
        ((float*)g_h2)[node * 32 + f] = acc;
        ((float*)g_out2)[node * 32 + f] = 0.f;
        float vs = acc * as2[f];
        float vd = acc * ad2[f];
#pragma unroll
        for (int o = 16; o > 0; o >>= 1) {
            vs += __shfl_down_sync(0xffffffffu, vs, o);
            vd += __shfl_down_sync(0xffffffffu, vd, o);
        }
        if (f == 0) {
            g_as2[node] = vs;
            g_ad2[node] = vd;
            g_den2[node] = 0.f;
        }
    }
}

// ---------------- kernel 5: layer-2 edge exp + denom --------------------------
__global__ void k_edge2a(const int* __restrict__ ei)
{
    int e = blockIdx.x * blockDim.x + threadIdx.x;
    if (e >= E_TOT) return;
    int s, d;
    if (e < N_EDGES) { s = ei[e]; d = ei[N_EDGES + e]; }
    else             { s = e - N_EDGES; d = s; }
    float w = __expf(lrelu(g_as2[s] + g_ad2[d]));
    g_ew2[e] = w;
    atomicAdd(&g_den2[d], w);
}

// ---------------- kernel 6: layer-2 aggregation (8 threads per edge) ----------
__global__ void k_edge2b(const int* __restrict__ ei)
{
    long long idx = (long long)blockIdx.x * blockDim.x + threadIdx.x;
    if (idx >= (long long)E_TOT * 8) return;
    int e = (int)(idx >> 3);
    int q = (int)(idx & 7);
    int s, d;
    if (e < N_EDGES) { s = ei[e]; d = ei[N_EDGES + e]; }
    else             { s = e - N_EDGES; d = s; }
    float att = g_ew2[e] / (g_den2[d] + 1e-16f);
    float4 hv = g_h2[s * 8 + q];
    float4 v = make_float4(att * hv.x, att * hv.y, att * hv.z, att * hv.w);
    atomicAdd(&g_out2[d * 8 + q], v);
}

// ---------------- kernel 7: elu(out2 + b2) in place ---------------------------
__global__ void k_node3(const float* __restrict__ b2)
{
    int idx = blockIdx.x * blockDim.x + threadIdx.x;
    if (idx >= N_NODES * 32) return;
    int c = idx & 31;
    float v = ((float*)g_out2)[idx] + b2[c];
    v = v > 0.f ? v : (__expf(v) - 1.f);
    ((float*)g_out2)[idx] = v;
}

// ---------------- kernel 8: segmented mean pool (binary search) + final linear -
__global__ void k_pool(const int* __restrict__ batch, const float* __restrict__ Wlin,
                       const float* __restrict__ blin, float* __restrict__ out)
{
    int g = blockIdx.x;                 // graph id
    int c = threadIdx.x;                // 0..31

    // lower_bound(batch, g) and lower_bound(batch, g+1) — batch is sorted
    int lo = 0, hi = N_NODES;
    while (lo < hi) { int m = (lo + hi) >> 1; if (batch[m] < g) lo = m + 1; else hi = m; }
    int start = lo;
    lo = start; hi = N_NODES;
    while (lo < hi) { int m = (lo + hi) >> 1; if (batch[m] < g + 1) lo = m + 1; else hi = m; }
    int end = lo;

    float s = 0.f;
    for (int n = start; n < end; n++)
        s += ((const float*)g_out2)[n * 32 + c];   // coalesced across warp

    float cnt = (float)((end - start) > 0 ? (end - start) : 1);
    float v = (s / cnt) * Wlin[c];
#pragma unroll
    for (int o = 16; o > 0; o >>= 1)
        v += __shfl_down_sync(0xffffffffu, v, o);
    if (c == 0) out[g] = v + blin[0];
}

// ---------------- launch --------------------------------------------------------
extern "C" void kernel_launch(void* const* d_in, const int* in_sizes, int n_in,
                              void* d_out, int out_size)
{
    const float* x     = (const float*)d_in[0];
    const int*   ei    = (const int*)  d_in[1];
    const int*   batch = (const int*)  d_in[2];
    const float* W1    = (const float*)d_in[3];
    const float* as1   = (const float*)d_in[4];
    const float* ad1   = (const float*)d_in[5];
    const float* b1    = (const float*)d_in[6];
    const float* W2    = (const float*)d_in[7];
    const float* as2   = (const float*)d_in[8];
    const float* ad2   = (const float*)d_in[9];
    const float* b2    = (const float*)d_in[10];
    const float* Wlin  = (const float*)d_in[11];
    const float* blin  = (const float*)d_in[12];
    float* out = (float*)d_out;

    k_node1<<<N_NODES, 128>>>(x, W1, as1, ad1);
    k_edge1a<<<(E_TOT + 255) / 256, 256>>>(ei);
    k_edge1b<<<(E_TOT * 32 + 255) / 256, 256>>>(ei);
    k_node2<<<N_NODES, 128>>>(b1, W2, as2, ad2);
    k_edge2a<<<(E_TOT + 255) / 256, 256>>>(ei);
    {
        long long t = (long long)E_TOT * 8;
        k_edge2b<<<(unsigned)((t + 255) / 256), 256>>>(ei);
    }
    k_node3<<<(N_NODES * 32 + 255) / 256, 256>>>(b2);
    k_pool<<<N_GRAPHS, 32>>>(batch, Wlin, blin, out);
}

// round 2
// speedup vs baseline: 1.0229x; 1.0229x over previous
#include <cuda_runtime.h>
#include <cuda_bf16.h>

#define N_NODES 50000
#define N_EDGES 800000
#define E_TOT   850000    // edges + self loops
#define N_GRAPHS 256
#define NEG_SLOPE 0.2f

// ---------------- scratch (device globals) ----------------
__device__ float4 g_h1  [N_NODES * 32];   // [N,128] layer-1 features
__device__ float4 g_out1[N_NODES * 32];   // [N,128] unnormalized numerator
__device__ float4 g_as1 [N_NODES];        // [N,4] alpha_src heads
__device__ float4 g_ad1 [N_NODES];        // [N,4] alpha_dst heads
__device__ float4 g_den1[N_NODES];        // [N,4] softmax denominators
__device__ float4 g_h2  [N_NODES * 8];    // [N,32] layer-2 features
__device__ float4 g_out2[N_NODES * 8];    // [N,32] unnormalized numerator
__device__ float  g_as2 [N_NODES];
__device__ float  g_ad2 [N_NODES];
__device__ float  g_den2[N_NODES];

__device__ __forceinline__ float lrelu(float t) {
    return t > 0.f ? t : NEG_SLOPE * t;
}
__device__ __forceinline__ float elu1(float v) {
    return v > 0.f ? v : (__expf(v) - 1.f);
}

// ---------------- kernel 1: h1 = x@W1, alphas, zero accumulators ----------------
__global__ void k_node1(const float* __restrict__ x, const float* __restrict__ W1,
                        const float* __restrict__ as1, const float* __restrict__ ad1)
{
    int node = blockIdx.x;
    int f = threadIdx.x;               // 0..127
    float x0 = x[node * 2], x1 = x[node * 2 + 1];
    float h = x0 * W1[f] + x1 * W1[128 + f];
    ((float*)g_h1)[node * 128 + f] = h;
    ((float*)g_out1)[node * 128 + f] = 0.f;

    int head = f >> 5, lane = f & 31;
    float vs = h * as1[f];
    float vd = h * ad1[f];
#pragma unroll
    for (int o = 16; o > 0; o >>= 1) {
        vs += __shfl_down_sync(0xffffffffu, vs, o);
        vd += __shfl_down_sync(0xffffffffu, vd, o);
    }
    if (lane == 0) {
        ((float*)g_as1)[node * 4 + head] = vs;
        ((float*)g_ad1)[node * 4 + head] = vd;
        ((float*)g_den1)[node * 4 + head] = 0.f;
    }
}

// ---------------- kernel 2: layer-1 fused edge pass --------------------------
// warp per edge: accumulate unnormalized numerator (w*h) and denominator
__global__ void k_edge1(const int* __restrict__ ei)
{
    int w = (blockIdx.x * blockDim.x + threadIdx.x) >> 5;
    if (w >= E_TOT) return;
    int lane = threadIdx.x & 31;
    int s, d;
    if (w < N_EDGES) { s = ei[w]; d = ei[N_EDGES + w]; }
    else             { s = w - N_EDGES; d = s; }

    float4 a = g_as1[s];               // broadcast loads
    float4 b = g_ad1[d];
    // each lane computes only its head's weight (1 MUFU instr per warp-step)
    float ah = (lane < 8) ? a.x : (lane < 16) ? a.y : (lane < 24) ? a.z : a.w;
    float bh = (lane < 8) ? b.x : (lane < 16) ? b.y : (lane < 24) ? b.z : b.w;
    float wh = __expf(lrelu(ah + bh));

    // denominator: gather head weights from lanes 0,8,16,24; lane0 does float4 RED
    float w1 = __shfl_sync(0xffffffffu, wh, 8);
    float w2 = __shfl_sync(0xffffffffu, wh, 16);
    float w3 = __shfl_sync(0xffffffffu, wh, 24);
    if (lane == 0)
        atomicAdd(&g_den1[d], make_float4(wh, w1, w2, w3));

    float4 hv = g_h1[s * 32 + lane];   // coalesced 512B gather
    atomicAdd(&g_out1[d * 32 + lane],
              make_float4(wh * hv.x, wh * hv.y, wh * hv.z, wh * hv.w));
}

// ---------------- kernel 3: normalize+elu, h2 = act@W2, alpha2, zero layer-2 ---
// W2 cached in shared once per block; warp-per-node matmul via shfl broadcast
__global__ void k_node2(const float* __restrict__ b1, const float* __restrict__ W2,
                        const float* __restrict__ as2, const float* __restrict__ ad2)
{
    __shared__ float W2s[128 * 32];
    __shared__ float b1s[128];
    for (int i = threadIdx.x; i < 128 * 32; i += blockDim.x) W2s[i] = W2[i];
    if (threadIdx.x < 128) b1s[threadIdx.x] = b1[threadIdx.x];
    __syncthreads();

    int lane = threadIdx.x & 31;
    int warp = (blockIdx.x * blockDim.x + threadIdx.x) >> 5;
    int nwarps = (gridDim.x * blockDim.x) >> 5;
    float asv = as2[lane];             // a_src2 is [1,32]
    float adv = ad2[lane];

    for (int node = warp; node < N_NODES; node += nwarps) {
        float4 den = g_den1[node];     // broadcast
        float dh = (lane < 8) ? den.x : (lane < 16) ? den.y : (lane < 24) ? den.z : den.w;
        float inv = 1.f / (dh + 1e-16f);
        float4 o = g_out1[node * 32 + lane];   // features lane*4..lane*4+3 (same head)
        float4 act;
        act.x = elu1(o.x * inv + b1s[lane * 4 + 0]);
        act.y = elu1(o.y * inv + b1s[lane * 4 + 1]);
        act.z = elu1(o.z * inv + b1s[lane * 4 + 2]);
        act.w = elu1(o.w * inv + b1s[lane * 4 + 3]);

        float acc = 0.f;
#pragma unroll
        for (int sl = 0; sl < 32; sl++) {
            float v0 = __shfl_sync(0xffffffffu, act.x, sl);
            float v1 = __shfl_sync(0xffffffffu, act.y, sl);
            float v2 = __shfl_sync(0xffffffffu, act.z, sl);
            float v3 = __shfl_sync(0xffffffffu, act.w, sl);
            int k = sl * 4;
            acc += v0 * W2s[(k + 0) * 32 + lane];
            acc += v1 * W2s[(k + 1) * 32 + lane];
            acc += v2 * W2s[(k + 2) * 32 + lane];
            acc += v3 * W2s[(k + 3) * 32 + lane];
        }

        ((float*)g_h2)[node * 32 + lane] = acc;
        ((float*)g_out2)[node * 32 + lane] = 0.f;

        float vs = acc * asv;
        float vd = acc * adv;
#pragma unroll
        for (int o2 = 16; o2 > 0; o2 >>= 1) {
            vs += __shfl_down_sync(0xffffffffu, vs, o2);
            vd += __shfl_down_sync(0xffffffffu, vd, o2);
        }
        if (lane == 0) {
            g_as2[node] = vs;
            g_ad2[node] = vd;
            g_den2[node] = 0.f;
        }
    }
}

// ---------------- kernel 4: layer-2 fused edge pass (8 threads per edge) ------
__global__ void k_edge2(const int* __restrict__ ei)
{
    int t = blockIdx.x * blockDim.x + threadIdx.x;
    int e = t >> 3;
    if (e >= E_TOT) return;
    int q = t & 7;
    int s, d;
    if (e < N_EDGES) { s = ei[e]; d = ei[N_EDGES + e]; }
    else             { s = e - N_EDGES; d = s; }

    float w = __expf(lrelu(g_as2[s] + g_ad2[d]));
    if (q == 0) atomicAdd(&g_den2[d], w);
    float4 hv = g_h2[s * 8 + q];
    atomicAdd(&g_out2[d * 8 + q],
              make_float4(w * hv.x, w * hv.y, w * hv.z, w * hv.w));
}

// ---------------- kernel 5: pool (fused normalize + bias + elu) + linear ------
__global__ void k_pool(const int* __restrict__ batch, const float* __restrict__ b2,
                       const float* __restrict__ Wlin, const float* __restrict__ blin,
                       float* __restrict__ out)
{
    __shared__ float red[4];
    int g = blockIdx.x;
    int c = threadIdx.x & 31;          // channel
    int wp = threadIdx.x >> 5;         // warp 0..3

    int lo = 0, hi = N_NODES;
    while (lo < hi) { int m = (lo + hi) >> 1; if (batch[m] < g) lo = m + 1; else hi = m; }
    int start = lo;
    lo = start; hi = N_NODES;
    while (lo < hi) { int m = (lo + hi) >> 1; if (batch[m] < g + 1) lo = m + 1; else hi = m; }
    int end = lo;

    float bc = b2[c];
    float s = 0.f;
    for (int n = start + wp; n < end; n += 4) {
        float inv = 1.f / (g_den2[n] + 1e-16f);
        float v = ((const float*)g_out2)[n * 32 + c];
        s += elu1(v * inv + bc);
    }

    float cnt = (float)((end - start) > 0 ? (end - start) : 1);
    float v = (s / cnt) * Wlin[c];
#pragma unroll
    for (int o = 16; o > 0; o >>= 1)
        v += __shfl_down_sync(0xffffffffu, v, o);
    if (c == 0) red[wp] = v;
    __syncthreads();
    if (threadIdx.x == 0)
        out[g] = red[0] + red[1] + red[2] + red[3] + blin[0];
}

// ---------------- launch --------------------------------------------------------
extern "C" void kernel_launch(void* const* d_in, const int* in_sizes, int n_in,
                              void* d_out, int out_size)
{
    const float* x     = (const float*)d_in[0];
    const int*   ei    = (const int*)  d_in[1];
    const int*   batch = (const int*)  d_in[2];
    const float* W1    = (const float*)d_in[3];
    const float* as1   = (const float*)d_in[4];
    const float* ad1   = (const float*)d_in[5];
    const float* b1    = (const float*)d_in[6];
    const float* W2    = (const float*)d_in[7];
    const float* as2   = (const float*)d_in[8];
    const float* ad2   = (const float*)d_in[9];
    const float* b2    = (const float*)d_in[10];
    const float* Wlin  = (const float*)d_in[11];
    const float* blin  = (const float*)d_in[12];
    float* out = (float*)d_out;

    k_node1<<<N_NODES, 128>>>(x, W1, as1, ad1);
    k_edge1<<<(E_TOT * 32 + 255) / 256, 256>>>(ei);
    k_node2<<<1184, 256>>>(b1, W2, as2, ad2);
    k_edge2<<<(E_TOT * 8 + 255) / 256, 256>>>(ei);
    k_pool<<<N_GRAPHS, 128>>>(batch, b2, Wlin, blin, out);
}

// round 4
// speedup vs baseline: 1.4044x; 1.3730x over previous
#include <cuda_runtime.h>
#include <cuda_bf16.h>

#define N_NODES 50000
#define N_EDGES 800000
#define E_TOT   850000
#define N_GRAPHS 256
#define NEG_SLOPE 0.2f

// ---------------- scratch ----------------
__device__ int   g_deg   [N_NODES];
__device__ int   g_rowptr[N_NODES + 1];
__device__ int   g_cursor[N_NODES];
__device__ int   g_col   [E_TOT];
__device__ int   g_bsum  [256];

// layer-1 alphas, factored exp form, layout [head][node]
__device__ float g_eas1 [4 * N_NODES];
__device__ float g_easp1[4 * N_NODES];
__device__ float g_ead1 [4 * N_NODES];
__device__ float g_eadp1[4 * N_NODES];

__device__ float4 g_h2[N_NODES * 8];      // [N,32]
__device__ float g_eas2 [N_NODES];
__device__ float g_easp2[N_NODES];
__device__ float g_ead2 [N_NODES];
__device__ float g_eadp2[N_NODES];

__device__ float g_pool[N_GRAPHS * 32];

__device__ __forceinline__ float elu1(float v) {
    return v > 0.f ? v : (__expf(v) - 1.f);
}

// ---------------- init: deg=1 (self loop), zero pool ----------------
__global__ void k_init()
{
    int i = blockIdx.x * blockDim.x + threadIdx.x;
    if (i < N_NODES) g_deg[i] = 1;
    if (i < N_GRAPHS * 32) g_pool[i] = 0.f;
}

// ---------------- histogram over dst ----------------
__global__ void k_hist(const int* __restrict__ ei)
{
    int e = blockIdx.x * blockDim.x + threadIdx.x;
    if (e < N_EDGES) atomicAdd(&g_deg[ei[N_EDGES + e]], 1);
}

// ---------------- 3-phase exclusive scan of deg -> rowptr ----------------
__global__ void k_scan1()
{
    __shared__ int wsum[8];
    int i = blockIdx.x * 256 + threadIdx.x;
    int v = (i < N_NODES) ? g_deg[i] : 0;
    int lane = threadIdx.x & 31, wp = threadIdx.x >> 5;
    int s = v;
#pragma unroll
    for (int o = 1; o < 32; o <<= 1) {
        int t = __shfl_up_sync(0xffffffffu, s, o);
        if (lane >= o) s += t;
    }
    if (lane == 31) wsum[wp] = s;
    __syncthreads();
    if (wp == 0) {
        int ws = (lane < 8) ? wsum[lane] : 0;
#pragma unroll
        for (int o = 1; o < 8; o <<= 1) {
            int t = __shfl_up_sync(0xffffffffu, ws, o);
            if (lane >= o) ws += t;
        }
        if (lane < 8) wsum[lane] = ws;
    }
    __syncthreads();
    int base = (wp > 0) ? wsum[wp - 1] : 0;
    int incl = s + base;
    if (i < N_NODES) g_rowptr[i] = incl - v;   // exclusive within block
    if (threadIdx.x == 255) g_bsum[blockIdx.x] = incl;
}

__global__ void k_scan2()   // one block: exclusive scan of 196 block sums
{
    __shared__ int wsum[8];
    int t = threadIdx.x;
    int v = (t < 196) ? g_bsum[t] : 0;
    int lane = t & 31, wp = t >> 5;
    int s = v;
#pragma unroll
    for (int o = 1; o < 32; o <<= 1) {
        int u = __shfl_up_sync(0xffffffffu, s, o);
        if (lane >= o) s += u;
    }
    if (lane == 31) wsum[wp] = s;
    __syncthreads();
    if (wp == 0) {
        int ws = (lane < 8) ? wsum[lane] : 0;
#pragma unroll
        for (int o = 1; o < 8; o <<= 1) {
            int u = __shfl_up_sync(0xffffffffu, ws, o);
            if (lane >= o) ws += u;
        }
        if (lane < 8) wsum[lane] = ws;
    }
    __syncthreads();
    int base = (wp > 0) ? wsum[wp - 1] : 0;
    g_bsum[t] = s + base - v;                  // exclusive
}

__global__ void k_scan3()
{
    int i = blockIdx.x * blockDim.x + threadIdx.x;
    if (i < N_NODES) {
        int r = g_rowptr[i] + g_bsum[i >> 8];
        g_rowptr[i] = r;
        g_cursor[i] = r;
    }
    if (i == 0) g_rowptr[N_NODES] = E_TOT;
}

// ---------------- scatter edges into CSR ----------------
__global__ void k_scatter(const int* __restrict__ ei)
{
    int e = blockIdx.x * blockDim.x + threadIdx.x;
    if (e >= E_TOT) return;
    int s, d;
    if (e < N_EDGES) { s = ei[e]; d = ei[N_EDGES + e]; }
    else             { s = e - N_EDGES; d = s; }
    int pos = atomicAdd(&g_cursor[d], 1);
    g_col[pos] = s;
}

// ---------------- node1: alphas only (h reconstructed later from x) ----------
__global__ void k_node1(const float* __restrict__ x, const float* __restrict__ W1,
                        const float* __restrict__ as1, const float* __restrict__ ad1)
{
    int node = blockIdx.x;
    int f = threadIdx.x;               // 0..127
    float x0 = x[node * 2], x1 = x[node * 2 + 1];
    float h = x0 * W1[f] + x1 * W1[128 + f];
    int head = f >> 5, lane = f & 31;
    float vs = h * as1[f];
    float vd = h * ad1[f];
#pragma unroll
    for (int o = 16; o > 0; o >>= 1) {
        vs += __shfl_down_sync(0xffffffffu, vs, o);
        vd += __shfl_down_sync(0xffffffffu, vd, o);
    }
    if (lane == 0) {
        int idx = head * N_NODES + node;
        g_eas1 [idx] = __expf(vs);
        g_easp1[idx] = __expf(NEG_SLOPE * vs);
        g_ead1 [idx] = __expf(vd);
        g_eadp1[idx] = __expf(NEG_SLOPE * vd);
    }
}

// ---------------- gat1: fused layer-1 gather + normalize + elu + W2 matmul ----
// warp per dst node
__global__ void k_gat1(const float* __restrict__ x, const float* __restrict__ W1,
                       const float* __restrict__ W2, const float* __restrict__ b1,
                       const float* __restrict__ as2, const float* __restrict__ ad2)
{
    __shared__ float W2s[128 * 32];
    __shared__ float b1s[128];
    for (int i = threadIdx.x; i < 128 * 32; i += blockDim.x) W2s[i] = W2[i];
    if (threadIdx.x < 128) b1s[threadIdx.x] = b1[threadIdx.x];
    __syncthreads();

    int lane = threadIdx.x & 31;
    int node = blockIdx.x * 8 + (threadIdx.x >> 5);
    int head = lane >> 3;

    // W1 slice for this lane's 4 output features (uniform 1KB table, L1-resident)
    float4 w1a, w1b;
    w1a.x = __ldg(&W1[lane * 4 + 0]);       w1a.y = __ldg(&W1[lane * 4 + 1]);
    w1a.z = __ldg(&W1[lane * 4 + 2]);       w1a.w = __ldg(&W1[lane * 4 + 3]);
    w1b.x = __ldg(&W1[128 + lane * 4 + 0]); w1b.y = __ldg(&W1[128 + lane * 4 + 1]);
    w1b.z = __ldg(&W1[128 + lane * 4 + 2]); w1b.w = __ldg(&W1[128 + lane * 4 + 3]);

    int hbase = head * N_NODES;
    float ed  = g_ead1 [hbase + node];
    float edp = g_eadp1[hbase + node];

    float4 num = make_float4(0.f, 0.f, 0.f, 0.f);
    float den = 0.f;
    int beg = g_rowptr[node], end = g_rowptr[node + 1];
    for (int j = beg; j < end; j++) {
        int s = g_col[j];
        float2 xs = ((const float2*)x)[s];
        float es  = g_eas1 [hbase + s];
        float esp = g_easp1[hbase + s];
        float p = es * ed;
        float w = (p > 1.f) ? p : esp * edp;
        num.x += w * (xs.x * w1a.x + xs.y * w1b.x);
        num.y += w * (xs.x * w1a.y + xs.y * w1b.y);
        num.z += w * (xs.x * w1a.z + xs.y * w1b.z);
        num.w += w * (xs.x * w1a.w + xs.y * w1b.w);
        den += w;
    }

    float inv = 1.f / (den + 1e-16f);
    float4 act;
    act.x = elu1(num.x * inv + b1s[lane * 4 + 0]);
    act.y = elu1(num.y * inv + b1s[lane * 4 + 1]);
    act.z = elu1(num.z * inv + b1s[lane * 4 + 2]);
    act.w = elu1(num.w * inv + b1s[lane * 4 + 3]);

    float acc = 0.f;
#pragma unroll
    for (int sl = 0; sl < 32; sl++) {
        float v0 = __shfl_sync(0xffffffffu, act.x, sl);
        float v1 = __shfl_sync(0xffffffffu, act.y, sl);
        float v2 = __shfl_sync(0xffffffffu, act.z, sl);
        float v3 = __shfl_sync(0xffffffffu, act.w, sl);
        int k = sl * 4;
        acc += v0 * W2s[(k + 0) * 32 + lane];
        acc += v1 * W2s[(k + 1) * 32 + lane];
        acc += v2 * W2s[(k + 2) * 32 + lane];
        acc += v3 * W2s[(k + 3) * 32 + lane];
    }

    ((float*)g_h2)[node * 32 + lane] = acc;

    float vs = acc * as2[lane];
    float vd = acc * ad2[lane];
#pragma unroll
    for (int o = 16; o > 0; o >>= 1) {
        vs += __shfl_down_sync(0xffffffffu, vs, o);
        vd += __shfl_down_sync(0xffffffffu, vd, o);
    }
    if (lane == 0) {
        g_eas2 [node] = __expf(vs);
        g_easp2[node] = __expf(NEG_SLOPE * vs);
        g_ead2 [node] = __expf(vd);
        g_eadp2[node] = __expf(NEG_SLOPE * vd);
    }
}

// ---------------- gat2: fused layer-2 gather + elu + pool ---------------------
__global__ void k_gat2(const int* __restrict__ batch, const float* __restrict__ b2)
{
    int lane = threadIdx.x & 31;
    int node = blockIdx.x * 8 + (threadIdx.x >> 5);

    float ed  = g_ead2 [node];
    float edp = g_eadp2[node];
    float acc = 0.f, den = 0.f;
    int beg = g_rowptr[node], end = g_rowptr[node + 1];
    for (int j = beg; j < end; j++) {
        int s = g_col[j];
        float es  = g_eas2 [s];
        float esp = g_easp2[s];
        float p = es * ed;
        float w = (p > 1.f) ? p : esp * edp;
        acc += w * ((const float*)g_h2)[s * 32 + lane];
        den += w;
    }
    float v = elu1(acc / (den + 1e-16f) + b2[lane]);
    atomicAdd(&g_pool[batch[node] * 32 + lane], v);
}

// ---------------- final: per-graph mean + linear ------------------------------
__global__ void k_final(const int* __restrict__ batch, const float* __restrict__ Wlin,
                        const float* __restrict__ blin, float* __restrict__ out)
{
    int g = blockIdx.x;
    int c = threadIdx.x;   // 0..31

    int lo = 0, hi = N_NODES;
    while (lo < hi) { int m = (lo + hi) >> 1; if (batch[m] < g) lo = m + 1; else hi = m; }
    int start = lo;
    lo = start; hi = N_NODES;
    while (lo < hi) { int m = (lo + hi) >> 1; if (batch[m] < g + 1) lo = m + 1; else hi = m; }
    int cnt = lo - start;

    float fc = (float)(cnt > 0 ? cnt : 1);
    float v = (g_pool[g * 32 + c] / fc) * Wlin[c];
#pragma unroll
    for (int o = 16; o > 0; o >>= 1)
        v += __shfl_down_sync(0xffffffffu, v, o);
    if (c == 0) out[g] = v + blin[0];
}

// ---------------- launch ------------------------------------------------------
extern "C" void kernel_launch(void* const* d_in, const int* in_sizes, int n_in,
                              void* d_out, int out_size)
{
    const float* x     = (const float*)d_in[0];
    const int*   ei    = (const int*)  d_in[1];
    const int*   batch = (const int*)  d_in[2];
    const float* W1    = (const float*)d_in[3];
    const float* as1   = (const float*)d_in[4];
    const float* ad1   = (const float*)d_in[5];
    const float* b1    = (const float*)d_in[6];
    const float* W2    = (const float*)d_in[7];
    const float* as2   = (const float*)d_in[8];
    const float* ad2   = (const float*)d_in[9];
    const float* b2    = (const float*)d_in[10];
    const float* Wlin  = (const float*)d_in[11];
    const float* blin  = (const float*)d_in[12];
    float* out = (float*)d_out;

    k_init<<<197, 256>>>();
    k_hist<<<(N_EDGES + 255) / 256, 256>>>(ei);
    k_scan1<<<196, 256>>>();
    k_scan2<<<1, 256>>>();
    k_scan3<<<197, 256>>>();
    k_scatter<<<(E_TOT + 255) / 256, 256>>>(ei);
    k_node1<<<N_NODES, 128>>>(x, W1, as1, ad1);
    k_gat1<<<6250, 256>>>(x, W1, W2, b1, as2, ad2);
    k_gat2<<<6250, 256>>>(batch, b2);
    k_final<<<N_GRAPHS, 32>>>(batch, Wlin, blin, out);
}

// round 5
// speedup vs baseline: 1.9414x; 1.3824x over previous
#include <cuda_runtime.h>
#include <cuda_bf16.h>

#define N_NODES 50000
#define N_EDGES 800000
#define E_TOT   850000
#define N_GRAPHS 256
#define NEG_SLOPE 0.2f

// ---------------- scratch ----------------
__device__ int    g_deg   [N_NODES];       // INVARIANT: zero at kernel_launch entry
__device__ int    g_rowptr[N_NODES + 1];
__device__ int    g_cursor[N_NODES];
__device__ int    g_col   [E_TOT];
__device__ int    g_bsum  [256];
__device__ float  g_proj  [16];            // psa[4], psb[4], pda[4], pdb[4]

__device__ float2 g_e1s[N_NODES * 4];      // (exp(as), exp(0.2*as)) per node,head
__device__ float2 g_e1d[N_NODES * 4];
__device__ float4 g_h2 [N_NODES * 8];      // [N,32]
__device__ float2 g_e2s[N_NODES];
__device__ float2 g_e2d[N_NODES];
__device__ float  g_pool[N_GRAPHS * 32];   // INVARIANT: zero at kernel_launch entry

__device__ __forceinline__ float elu1(float v) {
    return v > 0.f ? v : (__expf(v) - 1.f);
}

// ---------------- hist over dst + (block 0) W1/a projections ------------------
__global__ void k_hist(const int* __restrict__ ei, const float* __restrict__ W1,
                       const float* __restrict__ as1, const float* __restrict__ ad1)
{
    int t = blockIdx.x * blockDim.x + threadIdx.x;
    if (t < N_EDGES) atomicAdd(&g_deg[ei[N_EDGES + t]], 1);

    if (blockIdx.x == 0 && threadIdx.x < 128) {
        int f = threadIdx.x, lane = f & 31, head = f >> 5;
        float w0 = W1[f], w1 = W1[128 + f];
        float a = as1[f], b = ad1[f];
        float p0 = w0 * a, p1 = w1 * a, p2 = w0 * b, p3 = w1 * b;
#pragma unroll
        for (int o = 16; o > 0; o >>= 1) {
            p0 += __shfl_down_sync(0xffffffffu, p0, o);
            p1 += __shfl_down_sync(0xffffffffu, p1, o);
            p2 += __shfl_down_sync(0xffffffffu, p2, o);
            p3 += __shfl_down_sync(0xffffffffu, p3, o);
        }
        if (lane == 0) {
            g_proj[head]      = p0;
            g_proj[4 + head]  = p1;
            g_proj[8 + head]  = p2;
            g_proj[12 + head] = p3;
        }
    }
}

// ---------------- scan phase 1 (reads deg, RE-ZEROES it) ----------------------
__global__ void k_scan1()
{
    __shared__ int wsum[8];
    int i = blockIdx.x * 256 + threadIdx.x;
    int v = 0;
    if (i < N_NODES) { v = g_deg[i] + 1; g_deg[i] = 0; }   // +1 = self loop
    int lane = threadIdx.x & 31, wp = threadIdx.x >> 5;
    int s = v;
#pragma unroll
    for (int o = 1; o < 32; o <<= 1) {
        int t = __shfl_up_sync(0xffffffffu, s, o);
        if (lane >= o) s += t;
    }
    if (lane == 31) wsum[wp] = s;
    __syncthreads();
    if (wp == 0) {
        int ws = (lane < 8) ? wsum[lane] : 0;
#pragma unroll
        for (int o = 1; o < 8; o <<= 1) {
            int t = __shfl_up_sync(0xffffffffu, ws, o);
            if (lane >= o) ws += t;
        }
        if (lane < 8) wsum[lane] = ws;
    }
    __syncthreads();
    int base = (wp > 0) ? wsum[wp - 1] : 0;
    int incl = s + base;
    if (i < N_NODES) g_rowptr[i] = incl - v;
    if (threadIdx.x == 255) g_bsum[blockIdx.x] = incl;
}

// ---------------- scan phase 2 (1 block over 196 partials) --------------------
__global__ void k_scan2()
{
    __shared__ int wsum[8];
    int t = threadIdx.x;
    int v = (t < 196) ? g_bsum[t] : 0;
    int lane = t & 31, wp = t >> 5;
    int s = v;
#pragma unroll
    for (int o = 1; o < 32; o <<= 1) {
        int u = __shfl_up_sync(0xffffffffu, s, o);
        if (lane >= o) s += u;
    }
    if (lane == 31) wsum[wp] = s;
    __syncthreads();
    if (wp == 0) {
        int ws = (lane < 8) ? wsum[lane] : 0;
#pragma unroll
        for (int o = 1; o < 8; o <<= 1) {
            int u = __shfl_up_sync(0xffffffffu, ws, o);
            if (lane >= o) ws += u;
        }
        if (lane < 8) wsum[lane] = ws;
    }
    __syncthreads();
    int base = (wp > 0) ? wsum[wp - 1] : 0;
    g_bsum[t] = s + base - v;
}

// ---------------- scan phase 3 + layer-1 node alphas (rank-2) -----------------
__global__ void k_prep(const float* __restrict__ x)
{
    int i = blockIdx.x * blockDim.x + threadIdx.x;
    if (i == N_NODES) g_rowptr[N_NODES] = E_TOT;
    if (i >= N_NODES) return;

    int r = g_rowptr[i] + g_bsum[i >> 8];
    g_rowptr[i] = r;
    g_cursor[i] = r;

    float2 xv = ((const float2*)x)[i];
#pragma unroll
    for (int h = 0; h < 4; h++) {
        float vs = xv.x * g_proj[h]     + xv.y * g_proj[4 + h];
        float vd = xv.x * g_proj[8 + h] + xv.y * g_proj[12 + h];
        g_e1s[i * 4 + h] = make_float2(__expf(vs), __expf(NEG_SLOPE * vs));
        g_e1d[i * 4 + h] = make_float2(__expf(vd), __expf(NEG_SLOPE * vd));
    }
}

// ---------------- scatter edges into CSR --------------------------------------
__global__ void k_scatter(const int* __restrict__ ei)
{
    int e = blockIdx.x * blockDim.x + threadIdx.x;
    if (e >= E_TOT) return;
    int s, d;
    if (e < N_EDGES) { s = ei[e]; d = ei[N_EDGES + e]; }
    else             { s = e - N_EDGES; d = s; }
    int pos = atomicAdd(&g_cursor[d], 1);
    g_col[pos] = s;
}

// ---------------- gat1: rank-2 gather + normalize + elu + W2 matmul + alpha2 --
// warp per dst node; lanes split into 4 head-groups of 8 for the edge loop
__global__ void k_gat1(const float* __restrict__ x, const float* __restrict__ W1,
                       const float* __restrict__ W2, const float* __restrict__ b1,
                       const float* __restrict__ as2, const float* __restrict__ ad2)
{
    __shared__ float W2s[128 * 32];
    for (int i = threadIdx.x; i < 128 * 32; i += blockDim.x) W2s[i] = W2[i];
    __syncthreads();

    int lane = threadIdx.x & 31;
    int node = blockIdx.x * 8 + (threadIdx.x >> 5);
    int head = lane >> 3, l8 = lane & 7;

    float2 ed = g_e1d[node * 4 + head];         // group-uniform broadcast
    int beg = g_rowptr[node], end = g_rowptr[node + 1];

    float sx = 0.f, sy = 0.f, den = 0.f;
    for (int j = beg + l8; j < end; j += 8) {
        int s = g_col[j];
        float2 xs = ((const float2*)x)[s];
        float2 es = g_e1s[s * 4 + head];
        float p = es.x * ed.x;
        float w = (p > 1.f) ? p : es.y * ed.y;
        den += w;
        sx  += w * xs.x;
        sy  += w * xs.y;
    }
    // reduce within 8-lane group (leader l8==0 correct)
#pragma unroll
    for (int o = 4; o > 0; o >>= 1) {
        sx  += __shfl_down_sync(0xffffffffu, sx,  o, 8);
        sy  += __shfl_down_sync(0xffffffffu, sy,  o, 8);
        den += __shfl_down_sync(0xffffffffu, den, o, 8);
    }
    int src = head << 3;                        // group leader lane
    sx  = __shfl_sync(0xffffffffu, sx,  src);
    sy  = __shfl_sync(0xffffffffu, sy,  src);
    den = __shfl_sync(0xffffffffu, den, src);

    float4 w1a = *(const float4*)&W1[lane * 4];
    float4 w1b = *(const float4*)&W1[128 + lane * 4];
    float4 b1v = *(const float4*)&b1[lane * 4];
    float inv = 1.f / (den + 1e-16f);
    float4 act;
    act.x = elu1((sx * w1a.x + sy * w1b.x) * inv + b1v.x);
    act.y = elu1((sx * w1a.y + sy * w1b.y) * inv + b1v.y);
    act.z = elu1((sx * w1a.z + sy * w1b.z) * inv + b1v.z);
    act.w = elu1((sx * w1a.w + sy * w1b.w) * inv + b1v.w);

    float acc = 0.f;
#pragma unroll
    for (int sl = 0; sl < 32; sl++) {
        float v0 = __shfl_sync(0xffffffffu, act.x, sl);
        float v1 = __shfl_sync(0xffffffffu, act.y, sl);
        float v2 = __shfl_sync(0xffffffffu, act.z, sl);
        float v3 = __shfl_sync(0xffffffffu, act.w, sl);
        int k = sl * 4;
        acc += v0 * W2s[(k + 0) * 32 + lane];
        acc += v1 * W2s[(k + 1) * 32 + lane];
        acc += v2 * W2s[(k + 2) * 32 + lane];
        acc += v3 * W2s[(k + 3) * 32 + lane];
    }

    ((float*)g_h2)[node * 32 + lane] = acc;

    float vs = acc * as2[lane];
    float vd = acc * ad2[lane];
#pragma unroll
    for (int o = 16; o > 0; o >>= 1) {
        vs += __shfl_down_sync(0xffffffffu, vs, o);
        vd += __shfl_down_sync(0xffffffffu, vd, o);
    }
    if (lane == 0) {
        g_e2s[node] = make_float2(__expf(vs), __expf(NEG_SLOPE * vs));
        g_e2d[node] = make_float2(__expf(vd), __expf(NEG_SLOPE * vd));
    }
}

// ---------------- gat2: layer-2 gather + elu + pool atomics -------------------
__global__ void k_gat2(const int* __restrict__ batch, const float* __restrict__ b2)
{
    int lane = threadIdx.x & 31;
    int node = blockIdx.x * 8 + (threadIdx.x >> 5);

    float2 ed = g_e2d[node];
    float acc = 0.f, den = 0.f;
    int beg = g_rowptr[node], end = g_rowptr[node + 1];
#pragma unroll 2
    for (int j = beg; j < end; j++) {
        int s = g_col[j];
        float2 es = g_e2s[s];
        float p = es.x * ed.x;
        float w = (p > 1.f) ? p : es.y * ed.y;
        acc += w * ((const float*)g_h2)[s * 32 + lane];
        den += w;
    }
    float v = elu1(acc / (den + 1e-16f) + b2[lane]);
    atomicAdd(&g_pool[batch[node] * 32 + lane], v);
}

// ---------------- final: mean pool + linear (re-zeroes pool) ------------------
__global__ void k_final(const int* __restrict__ batch, const float* __restrict__ Wlin,
                        const float* __restrict__ blin, float* __restrict__ out)
{
    int g = blockIdx.x;
    int c = threadIdx.x;   // 0..31

    int lo = 0, hi = N_NODES;
    while (lo < hi) { int m = (lo + hi) >> 1; if (batch[m] < g) lo = m + 1; else hi = m; }
    int start = lo;
    lo = start; hi = N_NODES;
    while (lo < hi) { int m = (lo + hi) >> 1; if (batch[m] < g + 1) lo = m + 1; else hi = m; }
    int cnt = lo - start;

    float pv = g_pool[g * 32 + c];
    g_pool[g * 32 + c] = 0.f;                 // restore zero invariant

    float fc = (float)(cnt > 0 ? cnt : 1);
    float v = (pv / fc) * Wlin[c];
#pragma unroll
    for (int o = 16; o > 0; o >>= 1)
        v += __shfl_down_sync(0xffffffffu, v, o);
    if (c == 0) out[g] = v + blin[0];
}

// ---------------- launch ------------------------------------------------------
extern "C" void kernel_launch(void* const* d_in, const int* in_sizes, int n_in,
                              void* d_out, int out_size)
{
    const float* x     = (const float*)d_in[0];
    const int*   ei    = (const int*)  d_in[1];
    const int*   batch = (const int*)  d_in[2];
    const float* W1    = (const float*)d_in[3];
    const float* as1   = (const float*)d_in[4];
    const float* ad1   = (const float*)d_in[5];
    const float* b1    = (const float*)d_in[6];
    const float* W2    = (const float*)d_in[7];
    const float* as2   = (const float*)d_in[8];
    const float* ad2   = (const float*)d_in[9];
    const float* b2    = (const float*)d_in[10];
    const float* Wlin  = (const float*)d_in[11];
    const float* blin  = (const float*)d_in[12];
    float* out = (float*)d_out;

    k_hist<<<(N_EDGES + 255) / 256, 256>>>(ei, W1, as1, ad1);
    k_scan1<<<196, 256>>>();
    k_scan2<<<1, 256>>>();
    k_prep<<<197, 256>>>(x);
    k_scatter<<<(E_TOT + 255) / 256, 256>>>(ei);
    k_gat1<<<6250, 256>>>(x, W1, W2, b1, as2, ad2);
    k_gat2<<<6250, 256>>>(batch, b2);
    k_final<<<N_GRAPHS, 32>>>(batch, Wlin, blin, out);
}

// round 6
// speedup vs baseline: 2.0617x; 1.0620x over previous
#include <cuda_runtime.h>
#include <cuda_bf16.h>

#define N_NODES 50000
#define N_EDGES 800000
#define E_TOT   850000
#define N_GRAPHS 256
#define NEG_SLOPE 0.2f

// ---------------- scratch ----------------
__device__ int    g_deg   [N_NODES];       // INVARIANT: zero at kernel_launch entry
__device__ int    g_rowptr[N_NODES + 1];
__device__ int    g_cursor[N_NODES];
__device__ int    g_col   [E_TOT];
__device__ int    g_bsum  [256];
__device__ float  g_proj  [16];            // psa[4], psb[4], pda[4], pdb[4]

__device__ float2 g_e1s[N_NODES * 4];      // (exp(as), exp(0.2*as)) per node,head
__device__ float2 g_e1d[N_NODES * 4];
__device__ float4 g_h2 [N_NODES * 8];      // [N,32]
__device__ float2 g_e2s[N_NODES];
__device__ float2 g_e2d[N_NODES];
__device__ float  g_pool[N_GRAPHS * 32];   // INVARIANT: zero at kernel_launch entry

__device__ __forceinline__ float elu1(float v) {
    return v > 0.f ? v : (__expf(v) - 1.f);
}

// ---------------- hist over dst + (block 0) W1/a projections ------------------
__global__ void k_hist(const int* __restrict__ ei, const float* __restrict__ W1,
                       const float* __restrict__ as1, const float* __restrict__ ad1)
{
    int t = blockIdx.x * blockDim.x + threadIdx.x;
    if (t < N_EDGES) atomicAdd(&g_deg[ei[N_EDGES + t]], 1);

    if (blockIdx.x == 0 && threadIdx.x < 128) {
        int f = threadIdx.x, lane = f & 31, head = f >> 5;
        float w0 = W1[f], w1 = W1[128 + f];
        float a = as1[f], b = ad1[f];
        float p0 = w0 * a, p1 = w1 * a, p2 = w0 * b, p3 = w1 * b;
#pragma unroll
        for (int o = 16; o > 0; o >>= 1) {
            p0 += __shfl_down_sync(0xffffffffu, p0, o);
            p1 += __shfl_down_sync(0xffffffffu, p1, o);
            p2 += __shfl_down_sync(0xffffffffu, p2, o);
            p3 += __shfl_down_sync(0xffffffffu, p3, o);
        }
        if (lane == 0) {
            g_proj[head]      = p0;
            g_proj[4 + head]  = p1;
            g_proj[8 + head]  = p2;
            g_proj[12 + head] = p3;
        }
    }
}

// ---------------- scan phase 1 (block scan of deg) + layer-1 alphas -----------
__global__ void k_scan1(const float* __restrict__ x)
{
    __shared__ int wsum[8];
    int i = blockIdx.x * 256 + threadIdx.x;
    int v = 0;
    if (i < N_NODES) { v = g_deg[i] + 1; g_deg[i] = 0; }   // +1 = self loop; restore zero
    int lane = threadIdx.x & 31, wp = threadIdx.x >> 5;
    int s = v;
#pragma unroll
    for (int o = 1; o < 32; o <<= 1) {
        int t = __shfl_up_sync(0xffffffffu, s, o);
        if (lane >= o) s += t;
    }
    if (lane == 31) wsum[wp] = s;

    // layer-1 alphas (independent of scan) — hide MUFU under barrier/scan latency
    if (i < N_NODES) {
        float2 xv = ((const float2*)x)[i];
#pragma unroll
        for (int h = 0; h < 4; h++) {
            float vs = xv.x * g_proj[h]     + xv.y * g_proj[4 + h];
            float vd = xv.x * g_proj[8 + h] + xv.y * g_proj[12 + h];
            g_e1s[i * 4 + h] = make_float2(__expf(vs), __expf(NEG_SLOPE * vs));
            g_e1d[i * 4 + h] = make_float2(__expf(vd), __expf(NEG_SLOPE * vd));
        }
    }

    __syncthreads();
    if (wp == 0) {
        int ws = (lane < 8) ? wsum[lane] : 0;
#pragma unroll
        for (int o = 1; o < 8; o <<= 1) {
            int t = __shfl_up_sync(0xffffffffu, ws, o);
            if (lane >= o) ws += t;
        }
        if (lane < 8) wsum[lane] = ws;
    }
    __syncthreads();
    int base = (wp > 0) ? wsum[wp - 1] : 0;
    int incl = s + base;
    if (i < N_NODES) g_rowptr[i] = incl - v;   // exclusive within block
    if (threadIdx.x == 255) g_bsum[blockIdx.x] = incl;   // block total
}

// ---------------- prep: per-block reduce of bsum prefix + rowptr/cursor -------
__global__ void k_prep()
{
    __shared__ int ssum[8];
    int b = blockIdx.x;                 // 0..196
    int t = threadIdx.x;
    int lane = t & 31, wp = t >> 5;

    // base = sum of g_bsum[0..b)
    int v = (t < b) ? g_bsum[t] : 0;    // b <= 196 <= blockDim
#pragma unroll
    for (int o = 16; o > 0; o >>= 1)
        v += __shfl_down_sync(0xffffffffu, v, o);
    if (lane == 0) ssum[wp] = v;
    __syncthreads();
    int base = ssum[0] + ssum[1] + ssum[2] + ssum[3]
             + ssum[4] + ssum[5] + ssum[6] + ssum[7];

    int i = b * 256 + t;
    if (i < N_NODES) {
        int r = g_rowptr[i] + base;
        g_rowptr[i] = r;
        g_cursor[i] = r;
    }
    if (i == N_NODES) g_rowptr[N_NODES] = E_TOT;
}

// ---------------- scatter edges into CSR --------------------------------------
__global__ void k_scatter(const int* __restrict__ ei)
{
    int e = blockIdx.x * blockDim.x + threadIdx.x;
    if (e >= E_TOT) return;
    int s, d;
    if (e < N_EDGES) { s = ei[e]; d = ei[N_EDGES + e]; }
    else             { s = e - N_EDGES; d = s; }
    int pos = atomicAdd(&g_cursor[d], 1);
    g_col[pos] = s;
}

// ---------------- gat1: persistent; rank-2 gather + elu + W2 matmul + alpha2 --
// warp per dst node; lanes split into 4 head-groups of 8 for the edge loop
__global__ void __launch_bounds__(256) k_gat1(
    const float* __restrict__ x, const float* __restrict__ W1,
    const float* __restrict__ W2, const float* __restrict__ b1,
    const float* __restrict__ as2, const float* __restrict__ ad2)
{
    __shared__ float W2s[128 * 32];
    for (int i = threadIdx.x; i < 128 * 32; i += blockDim.x) W2s[i] = W2[i];
    __syncthreads();

    int lane = threadIdx.x & 31;
    int head = lane >> 3, l8 = lane & 7;

    // hoisted per-lane constants
    float4 w1a = *(const float4*)&W1[lane * 4];
    float4 w1b = *(const float4*)&W1[128 + lane * 4];
    float4 b1v = *(const float4*)&b1[lane * 4];
    float asv = as2[lane];
    float adv = ad2[lane];

    for (int tile = blockIdx.x; tile < N_NODES / 8; tile += gridDim.x) {
        int node = tile * 8 + (threadIdx.x >> 5);

        float2 ed = g_e1d[node * 4 + head];     // group-uniform broadcast
        int beg = g_rowptr[node], end = g_rowptr[node + 1];

        float sx = 0.f, sy = 0.f, den = 0.f;
        for (int j = beg + l8; j < end; j += 8) {
            int s = g_col[j];
            float2 xs = ((const float2*)x)[s];
            float2 es = g_e1s[s * 4 + head];
            float p = es.x * ed.x;
            float w = (p > 1.f) ? p : es.y * ed.y;
            den += w;
            sx  += w * xs.x;
            sy  += w * xs.y;
        }
#pragma unroll
        for (int o = 4; o > 0; o >>= 1) {
            sx  += __shfl_down_sync(0xffffffffu, sx,  o, 8);
            sy  += __shfl_down_sync(0xffffffffu, sy,  o, 8);
            den += __shfl_down_sync(0xffffffffu, den, o, 8);
        }
        int src = head << 3;
        sx  = __shfl_sync(0xffffffffu, sx,  src);
        sy  = __shfl_sync(0xffffffffu, sy,  src);
        den = __shfl_sync(0xffffffffu, den, src);

        float inv = 1.f / (den + 1e-16f);
        float4 act;
        act.x = elu1((sx * w1a.x + sy * w1b.x) * inv + b1v.x);
        act.y = elu1((sx * w1a.y + sy * w1b.y) * inv + b1v.y);
        act.z = elu1((sx * w1a.z + sy * w1b.z) * inv + b1v.z);
        act.w = elu1((sx * w1a.w + sy * w1b.w) * inv + b1v.w);

        float acc = 0.f;
#pragma unroll
        for (int sl = 0; sl < 32; sl++) {
            float v0 = __shfl_sync(0xffffffffu, act.x, sl);
            float v1 = __shfl_sync(0xffffffffu, act.y, sl);
            float v2 = __shfl_sync(0xffffffffu, act.z, sl);
            float v3 = __shfl_sync(0xffffffffu, act.w, sl);
            int k = sl * 4;
            acc += v0 * W2s[(k + 0) * 32 + lane];
            acc += v1 * W2s[(k + 1) * 32 + lane];
            acc += v2 * W2s[(k + 2) * 32 + lane];
            acc += v3 * W2s[(k + 3) * 32 + lane];
        }

        ((float*)g_h2)[node * 32 + lane] = acc;

        float vs = acc * asv;
        float vd = acc * adv;
#pragma unroll
        for (int o = 16; o > 0; o >>= 1) {
            vs += __shfl_down_sync(0xffffffffu, vs, o);
            vd += __shfl_down_sync(0xffffffffu, vd, o);
        }
        if (lane == 0) {
            g_e2s[node] = make_float2(__expf(vs), __expf(NEG_SLOPE * vs));
            g_e2d[node] = make_float2(__expf(vd), __expf(NEG_SLOPE * vd));
        }
    }
}

// ---------------- gat2: layer-2 gather + elu + pool atomics -------------------
__global__ void k_gat2(const int* __restrict__ batch, const float* __restrict__ b2)
{
    int lane = threadIdx.x & 31;
    int node = blockIdx.x * 8 + (threadIdx.x >> 5);

    float2 ed = g_e2d[node];
    float acc = 0.f, den = 0.f;
    int beg = g_rowptr[node], end = g_rowptr[node + 1];
#pragma unroll 2
    for (int j = beg; j < end; j++) {
        int s = g_col[j];
        float2 es = g_e2s[s];
        float p = es.x * ed.x;
        float w = (p > 1.f) ? p : es.y * ed.y;
        acc += w * ((const float*)g_h2)[s * 32 + lane];
        den += w;
    }
    float v = elu1(acc / (den + 1e-16f) + b2[lane]);
    atomicAdd(&g_pool[batch[node] * 32 + lane], v);
}

// ---------------- final: mean pool + linear (re-zeroes pool) ------------------
__global__ void k_final(const int* __restrict__ batch, const float* __restrict__ Wlin,
                        const float* __restrict__ blin, float* __restrict__ out)
{
    int g = blockIdx.x;
    int c = threadIdx.x;   // 0..31

    int lo = 0, hi = N_NODES;
    while (lo < hi) { int m = (lo + hi) >> 1; if (batch[m] < g) lo = m + 1; else hi = m; }
    int start = lo;
    lo = start; hi = N_NODES;
    while (lo < hi) { int m = (lo + hi) >> 1; if (batch[m] < g + 1) lo = m + 1; else hi = m; }
    int cnt = lo - start;

    float pv = g_pool[g * 32 + c];
    g_pool[g * 32 + c] = 0.f;                 // restore zero invariant

    float fc = (float)(cnt > 0 ? cnt : 1);
    float v = (pv / fc) * Wlin[c];
#pragma unroll
    for (int o = 16; o > 0; o >>= 1)
        v += __shfl_down_sync(0xffffffffu, v, o);
    if (c == 0) out[g] = v + blin[0];
}

// ---------------- launch ------------------------------------------------------
extern "C" void kernel_launch(void* const* d_in, const int* in_sizes, int n_in,
                              void* d_out, int out_size)
{
    const float* x     = (const float*)d_in[0];
    const int*   ei    = (const int*)  d_in[1];
    const int*   batch = (const int*)  d_in[2];
    const float* W1    = (const float*)d_in[3];
    const float* as1   = (const float*)d_in[4];
    const float* ad1   = (const float*)d_in[5];
    const float* b1    = (const float*)d_in[6];
    const float* W2    = (const float*)d_in[7];
    const float* as2   = (const float*)d_in[8];
    const float* ad2   = (const float*)d_in[9];
    const float* b2    = (const float*)d_in[10];
    const float* Wlin  = (const float*)d_in[11];
    const float* blin  = (const float*)d_in[12];
    float* out = (float*)d_out;

    k_hist<<<(N_EDGES + 255) / 256, 256>>>(ei, W1, as1, ad1);
    k_scan1<<<196, 256>>>(x);
    k_prep<<<197, 256>>>();
    k_scatter<<<(E_TOT + 255) / 256, 256>>>(ei);
    k_gat1<<<1184, 256>>>(x, W1, W2, b1, as2, ad2);
    k_gat2<<<6250, 256>>>(batch, b2);
    k_final<<<N_GRAPHS, 32>>>(batch, Wlin, blin, out);
}